// round 1
// baseline (speedup 1.0000x reference)
#include <cuda_runtime.h>
#include <cstddef>

#define BATCH_N 16384
#define SEQ_N   512
#define HID_N   5
#define G4      (4*HID_N)          // 20
#define FLAT_N  (SEQ_N*HID_N)      // 2560

// Scratch for the collapsed linear head: Weff = W2 @ W1  (1 x 2560), beff = W2@b1 + b2
__device__ float g_Weff[FLAT_N];
__device__ float g_beff;

// ---------------------------------------------------------------------------
// Kernel 1: collapse the two linear layers (no nonlinearity between them).
// W1: (512, 2560) row-major, W2: (1, 512). Weff[j] = sum_k W2[k] * W1[k,j].
// Coalesced across j. ~1.3 MFLOP, negligible.
// ---------------------------------------------------------------------------
__global__ void weff_kernel(const float* __restrict__ W1,
                            const float* __restrict__ b1,
                            const float* __restrict__ W2,
                            const float* __restrict__ b2)
{
    int j = blockIdx.x * blockDim.x + threadIdx.x;
    if (j < FLAT_N) {
        float acc = 0.0f;
        #pragma unroll 8
        for (int k = 0; k < 512; ++k)
            acc = fmaf(W2[k], W1[(size_t)k * FLAT_N + j], acc);
        g_Weff[j] = acc;
    }
    if (j == 0) {
        float acc = b2[0];
        for (int k = 0; k < 512; ++k)
            acc = fmaf(W2[k], b1[k], acc);
        g_beff = acc;
    }
}

// ---------------------------------------------------------------------------
// Activation helpers: EX2 + RCP based (MUFU.EX2 / MUFU.RCP, ~1e-7 abs error).
// Deliberately NOT tanh.approx in this round — keep recurrence error tiny.
// ---------------------------------------------------------------------------
__device__ __forceinline__ float sigmoid_f(float v) {
    return __fdividef(1.0f, 1.0f + __expf(-v));
}
__device__ __forceinline__ float tanh_f(float v) {
    float e = __expf(-2.0f * v);
    return __fdividef(1.0f - e, 1.0f + e);
}

// ---------------------------------------------------------------------------
// Kernel 2: one thread per batch element. Full 2-layer LSTM recurrence in
// registers; weights in shared memory (uniform-address broadcast LDS);
// linear head folded into the step loop via Weff. Output: 1 float/thread.
// ---------------------------------------------------------------------------
__global__ void __launch_bounds__(128)
lstm_fused_kernel(const float* __restrict__ x,
                  const float* __restrict__ Wih0, const float* __restrict__ Whh0,
                  const float* __restrict__ bih0, const float* __restrict__ bhh0,
                  const float* __restrict__ Wih1, const float* __restrict__ Whh1,
                  const float* __restrict__ bih1, const float* __restrict__ bhh1,
                  float* __restrict__ out)
{
    __shared__ float sWih0[G4];
    __shared__ float sB0[G4];
    __shared__ float sB1[G4];
    __shared__ float sWhh0[G4 * HID_N];
    __shared__ float sWih1[G4 * HID_N];
    __shared__ float sWhh1[G4 * HID_N];
    __shared__ float sWeff[FLAT_N];

    const int t = threadIdx.x;
    if (t < G4) {
        sWih0[t] = Wih0[t];
        sB0[t]   = bih0[t] + bhh0[t];
        sB1[t]   = bih1[t] + bhh1[t];
    }
    for (int i = t; i < G4 * HID_N; i += blockDim.x) {
        sWhh0[i] = Whh0[i];
        sWih1[i] = Wih1[i];
        sWhh1[i] = Whh1[i];
    }
    for (int i = t; i < FLAT_N; i += blockDim.x)
        sWeff[i] = g_Weff[i];
    __syncthreads();

    const int b = blockIdx.x * blockDim.x + t;
    const float* __restrict__ xr = x + (size_t)b * SEQ_N;

    float h0[HID_N], c0[HID_N], h1[HID_N], c1[HID_N];
    #pragma unroll
    for (int j = 0; j < HID_N; ++j) { h0[j] = 0.f; c0[j] = 0.f; h1[j] = 0.f; c1[j] = 0.f; }

    float acc = g_beff;

    #pragma unroll 1
    for (int s = 0; s < SEQ_N; ++s) {
        const float xin = __ldg(&xr[s]);
        float g[G4];

        // ---- layer 0 gates: b + Wih0*x + Whh0 @ h0 ----
        #pragma unroll
        for (int gi = 0; gi < G4; ++gi) {
            float a = fmaf(sWih0[gi], xin, sB0[gi]);
            #pragma unroll
            for (int j = 0; j < HID_N; ++j)
                a = fmaf(sWhh0[gi * HID_N + j], h0[j], a);
            g[gi] = a;
        }
        // ---- layer 0 state update (gate order i,f,g,o) ----
        #pragma unroll
        for (int j = 0; j < HID_N; ++j) {
            float ig = sigmoid_f(g[j]);
            float fg = sigmoid_f(g[HID_N + j]);
            float gg = tanh_f   (g[2 * HID_N + j]);
            float og = sigmoid_f(g[3 * HID_N + j]);
            float c  = fmaf(fg, c0[j], ig * gg);
            c0[j] = c;
            h0[j] = og * tanh_f(c);
        }

        // ---- layer 1 gates: b + Wih1 @ h0 + Whh1 @ h1 ----
        #pragma unroll
        for (int gi = 0; gi < G4; ++gi) {
            float a = sB1[gi];
            #pragma unroll
            for (int j = 0; j < HID_N; ++j)
                a = fmaf(sWih1[gi * HID_N + j], h0[j], a);
            #pragma unroll
            for (int j = 0; j < HID_N; ++j)
                a = fmaf(sWhh1[gi * HID_N + j], h1[j], a);
            g[gi] = a;
        }
        // ---- layer 1 state update ----
        #pragma unroll
        for (int j = 0; j < HID_N; ++j) {
            float ig = sigmoid_f(g[j]);
            float fg = sigmoid_f(g[HID_N + j]);
            float gg = tanh_f   (g[2 * HID_N + j]);
            float og = sigmoid_f(g[3 * HID_N + j]);
            float c  = fmaf(fg, c1[j], ig * gg);
            c1[j] = c;
            h1[j] = og * tanh_f(c);
        }

        // ---- fold linear head: acc += h1 . Weff[s*5 : s*5+5] ----
        #pragma unroll
        for (int j = 0; j < HID_N; ++j)
            acc = fmaf(h1[j], sWeff[s * HID_N + j], acc);
    }

    out[b] = acc;
}

// ---------------------------------------------------------------------------
// Harness entry. Inputs in metadata order:
// x, Wih0, Whh0, bih0, bhh0, Wih1, Whh1, bih1, bhh1, W1, b1, W2, b2
// ---------------------------------------------------------------------------
extern "C" void kernel_launch(void* const* d_in, const int* in_sizes, int n_in,
                              void* d_out, int out_size)
{
    const float* x    = (const float*)d_in[0];
    const float* Wih0 = (const float*)d_in[1];
    const float* Whh0 = (const float*)d_in[2];
    const float* bih0 = (const float*)d_in[3];
    const float* bhh0 = (const float*)d_in[4];
    const float* Wih1 = (const float*)d_in[5];
    const float* Whh1 = (const float*)d_in[6];
    const float* bih1 = (const float*)d_in[7];
    const float* bhh1 = (const float*)d_in[8];
    const float* W1   = (const float*)d_in[9];
    const float* b1   = (const float*)d_in[10];
    const float* W2   = (const float*)d_in[11];
    const float* b2   = (const float*)d_in[12];
    float* out = (float*)d_out;

    // 1) Collapse the linear head (same stream -> graph-ordered before main kernel)
    weff_kernel<<<(FLAT_N + 511) / 512, 512>>>(W1, b1, W2, b2);

    // 2) Fused 2-layer LSTM + folded head: 16384 threads, 1 per batch element.
    lstm_fused_kernel<<<BATCH_N / 128, 128>>>(x, Wih0, Whh0, bih0, bhh0,
                                              Wih1, Whh1, bih1, bhh1, out);
}

// round 4
// speedup vs baseline: 1.5841x; 1.5841x over previous
#include <cuda_runtime.h>
#include <cstddef>

#define BATCH_N 16384
#define SEQ_N   512
#define HID_N   5
#define G4      20          // 4*H
#define NPAIR   10          // G4/2 packed gate pairs
#define FLAT_N  2560        // SEQ_N*HID_N

// Collapsed linear head: Weff = W2 @ W1 (1 x 2560), beff = W2@b1 + b2
__device__ float g_Weff[FLAT_N];
__device__ float g_beff;

// ---------------------------------------------------------------------------
// Kernel 1: collapse the two linear layers (no nonlinearity between them).
// ---------------------------------------------------------------------------
__global__ void weff_kernel(const float* __restrict__ W1,
                            const float* __restrict__ b1,
                            const float* __restrict__ W2,
                            const float* __restrict__ b2)
{
    int j = blockIdx.x * blockDim.x + threadIdx.x;
    if (j < FLAT_N) {
        float acc = 0.0f;
        #pragma unroll 8
        for (int k = 0; k < 512; ++k)
            acc = fmaf(W2[k], W1[(size_t)k * FLAT_N + j], acc);
        g_Weff[j] = acc;
    }
    if (j == 0) {
        float acc = b2[0];
        for (int k = 0; k < 512; ++k)
            acc = fmaf(W2[k], b1[k], acc);
        g_beff = acc;
    }
}

// ---------------------------------------------------------------------------
// Packed f32x2 + fast-activation primitives (sm_100+ FFMA2, MUFU.TANH)
// ---------------------------------------------------------------------------
typedef unsigned long long u64;

__device__ __forceinline__ u64 pack2(float lo, float hi) {
    u64 r; asm("mov.b64 %0, {%1, %2};" : "=l"(r) : "f"(lo), "f"(hi)); return r;
}
__device__ __forceinline__ void unpack2(u64 v, float& lo, float& hi) {
    asm("mov.b64 {%0, %1}, %2;" : "=f"(lo), "=f"(hi) : "l"(v));
}
__device__ __forceinline__ u64 fma2(u64 a, u64 b, u64 c) {
    u64 d; asm("fma.rn.f32x2 %0, %1, %2, %3;" : "=l"(d) : "l"(a), "l"(b), "l"(c)); return d;
}
__device__ __forceinline__ float tanh_fast(float x) {
    float y; asm("tanh.approx.f32 %0, %1;" : "=f"(y) : "f"(x)); return y;
}
__device__ __forceinline__ float sig_fast(float x) {
    return fmaf(0.5f, tanh_fast(0.5f * x), 0.5f);
}

// ---------------------------------------------------------------------------
// Kernel 2: one thread per batch element; gate matvecs as 10 packed f32x2
// chains; weights pre-packed (gate 2p, gate 2p+1) in shared (LDS.64).
// ---------------------------------------------------------------------------
__global__ void __launch_bounds__(128)
lstm_fused_kernel(const float* __restrict__ x,
                  const float* __restrict__ Wih0, const float* __restrict__ Whh0,
                  const float* __restrict__ bih0, const float* __restrict__ bhh0,
                  const float* __restrict__ Wih1, const float* __restrict__ Whh1,
                  const float* __restrict__ bih1, const float* __restrict__ bhh1,
                  float* __restrict__ out)
{
    __shared__ u64 sWih0p[NPAIR];
    __shared__ u64 sB0p[NPAIR];
    __shared__ u64 sB1p[NPAIR];
    __shared__ u64 sWhh0p[NPAIR * HID_N];
    __shared__ u64 sWih1p[NPAIR * HID_N];
    __shared__ u64 sWhh1p[NPAIR * HID_N];
    __shared__ u64 sWeffA[SEQ_N];       // (Weff[5s], Weff[5s+1])
    __shared__ u64 sWeffB[SEQ_N];       // (Weff[5s+2], Weff[5s+3])
    __shared__ float sWeffC[SEQ_N];     //  Weff[5s+4]

    const int t = threadIdx.x;

    // pair p holds gates (2p, 2p+1); W row-major (20 x 5): gate g, col j at [g*5+j]
    if (t < NPAIR) {
        sWih0p[t] = pack2(Wih0[2 * t], Wih0[2 * t + 1]);
        sB0p[t]   = pack2(bih0[2 * t] + bhh0[2 * t], bih0[2 * t + 1] + bhh0[2 * t + 1]);
        sB1p[t]   = pack2(bih1[2 * t] + bhh1[2 * t], bih1[2 * t + 1] + bhh1[2 * t + 1]);
    }
    for (int i = t; i < NPAIR * HID_N; i += blockDim.x) {
        int p = i / HID_N, j = i % HID_N;
        sWhh0p[i] = pack2(Whh0[10 * p + j], Whh0[10 * p + 5 + j]);
        sWih1p[i] = pack2(Wih1[10 * p + j], Wih1[10 * p + 5 + j]);
        sWhh1p[i] = pack2(Whh1[10 * p + j], Whh1[10 * p + 5 + j]);
    }
    for (int s = t; s < SEQ_N; s += blockDim.x) {
        sWeffA[s] = pack2(g_Weff[5 * s + 0], g_Weff[5 * s + 1]);
        sWeffB[s] = pack2(g_Weff[5 * s + 2], g_Weff[5 * s + 3]);
        sWeffC[s] = g_Weff[5 * s + 4];
    }
    __syncthreads();

    const int b = blockIdx.x * blockDim.x + t;
    const float* __restrict__ xr = x + (size_t)b * SEQ_N;

    u64 hh0[HID_N], hh1[HID_N];          // broadcast-packed (h, h)
    float c0[HID_N], c1[HID_N];
    #pragma unroll
    for (int j = 0; j < HID_N; ++j) {
        hh0[j] = 0ull; hh1[j] = 0ull; c0[j] = 0.f; c1[j] = 0.f;
    }

    float accS = g_beff;
    u64 acc2 = 0ull;

    #pragma unroll 1
    for (int s = 0; s < SEQ_N; ++s) {
        const float xin = __ldg(&xr[s]);
        const u64 xx = pack2(xin, xin);
        float g[G4];

        // ---- layer 0 gates: 10 packed chains of 6 FFMA2 ----
        #pragma unroll
        for (int p = 0; p < NPAIR; ++p) {
            u64 a = fma2(sWih0p[p], xx, sB0p[p]);
            #pragma unroll
            for (int j = 0; j < HID_N; ++j)
                a = fma2(sWhh0p[p * HID_N + j], hh0[j], a);
            unpack2(a, g[2 * p], g[2 * p + 1]);
        }
        // ---- layer 0 state update (gate order i,f,g,o) ----
        #pragma unroll
        for (int j = 0; j < HID_N; ++j) {
            float ig = sig_fast (g[j]);
            float fg = sig_fast (g[HID_N + j]);
            float gg = tanh_fast(g[2 * HID_N + j]);
            float og = sig_fast (g[3 * HID_N + j]);
            float c  = fmaf(fg, c0[j], ig * gg);
            c0[j] = c;
            float h = og * tanh_fast(c);
            hh0[j] = pack2(h, h);
        }

        // ---- layer 1 gates: 10 packed chains of 10 FFMA2 ----
        #pragma unroll
        for (int p = 0; p < NPAIR; ++p) {
            u64 a = sB1p[p];
            #pragma unroll
            for (int j = 0; j < HID_N; ++j)
                a = fma2(sWih1p[p * HID_N + j], hh0[j], a);
            #pragma unroll
            for (int j = 0; j < HID_N; ++j)
                a = fma2(sWhh1p[p * HID_N + j], hh1[j], a);
            unpack2(a, g[2 * p], g[2 * p + 1]);
        }
        // ---- layer 1 state update + keep scalar h for the head ----
        float h1v[HID_N];
        #pragma unroll
        for (int j = 0; j < HID_N; ++j) {
            float ig = sig_fast (g[j]);
            float fg = sig_fast (g[HID_N + j]);
            float gg = tanh_fast(g[2 * HID_N + j]);
            float og = sig_fast (g[3 * HID_N + j]);
            float c  = fmaf(fg, c1[j], ig * gg);
            c1[j] = c;
            float h = og * tanh_fast(c);
            h1v[j] = h;
            hh1[j] = pack2(h, h);
        }

        // ---- folded head: acc += h1 . Weff[5s : 5s+5] (packed) ----
        acc2 = fma2(pack2(h1v[0], h1v[1]), sWeffA[s], acc2);
        acc2 = fma2(pack2(h1v[2], h1v[3]), sWeffB[s], acc2);
        accS = fmaf(h1v[4], sWeffC[s], accS);
    }

    float alo, ahi;
    unpack2(acc2, alo, ahi);
    out[b] = accS + alo + ahi;
}

// ---------------------------------------------------------------------------
// Harness entry. Inputs in metadata order:
// x, Wih0, Whh0, bih0, bhh0, Wih1, Whh1, bih1, bhh1, W1, b1, W2, b2
// ---------------------------------------------------------------------------
extern "C" void kernel_launch(void* const* d_in, const int* in_sizes, int n_in,
                              void* d_out, int out_size)
{
    const float* x    = (const float*)d_in[0];
    const float* Wih0 = (const float*)d_in[1];
    const float* Whh0 = (const float*)d_in[2];
    const float* bih0 = (const float*)d_in[3];
    const float* bhh0 = (const float*)d_in[4];
    const float* Wih1 = (const float*)d_in[5];
    const float* Whh1 = (const float*)d_in[6];
    const float* bih1 = (const float*)d_in[7];
    const float* bhh1 = (const float*)d_in[8];
    const float* W1   = (const float*)d_in[9];
    const float* b1   = (const float*)d_in[10];
    const float* W2   = (const float*)d_in[11];
    const float* b2   = (const float*)d_in[12];
    float* out = (float*)d_out;

    weff_kernel<<<(FLAT_N + 511) / 512, 512>>>(W1, b1, W2, b2);

    lstm_fused_kernel<<<BATCH_N / 128, 128>>>(x, Wih0, Whh0, bih0, bhh0,
                                              Wih1, Whh1, bih1, bhh1, out);
}

// round 6
// speedup vs baseline: 1.6359x; 1.0327x over previous
#include <cuda_runtime.h>
#include <cstddef>

#define BATCH_N 16384
#define SEQ_N   512
#define HID_N   5
#define FLAT_N  2560        // SEQ_N*HID_N

// Collapsed linear head: Weff = W2 @ W1 (1 x 2560), beff = W2@b1 + b2
__device__ float g_Weff[FLAT_N];
__device__ float g_beff;

// ---------------------------------------------------------------------------
// Kernel 1: collapse the two linear layers (no nonlinearity between them).
// ---------------------------------------------------------------------------
__global__ void weff_kernel(const float* __restrict__ W1,
                            const float* __restrict__ b1,
                            const float* __restrict__ W2,
                            const float* __restrict__ b2)
{
    int j = blockIdx.x * blockDim.x + threadIdx.x;
    if (j < FLAT_N) {
        float acc = 0.0f;
        #pragma unroll 8
        for (int k = 0; k < 512; ++k)
            acc = fmaf(W2[k], W1[(size_t)k * FLAT_N + j], acc);
        g_Weff[j] = acc;
    }
    if (j == 0) {
        float acc = b2[0];
        for (int k = 0; k < 512; ++k)
            acc = fmaf(W2[k], b1[k], acc);
        g_beff = acc;
    }
}

// ---------------------------------------------------------------------------
// Packed f32x2 + fast-activation primitives
// ---------------------------------------------------------------------------
typedef unsigned long long u64;

__device__ __forceinline__ u64 pack2(float lo, float hi) {
    u64 r; asm("mov.b64 %0, {%1, %2};" : "=l"(r) : "f"(lo), "f"(hi)); return r;
}
__device__ __forceinline__ void unpack2(u64 v, float& lo, float& hi) {
    asm("mov.b64 {%0, %1}, %2;" : "=f"(lo), "=f"(hi) : "l"(v));
}
__device__ __forceinline__ u64 fma2(u64 a, u64 b, u64 c) {
    u64 d; asm("fma.rn.f32x2 %0, %1, %2, %3;" : "=l"(d) : "l"(a), "l"(b), "l"(c)); return d;
}
__device__ __forceinline__ float tanh_fast(float x) {
    float y; asm("tanh.approx.f32 %0, %1;" : "=f"(y) : "f"(x)); return y;
}
__device__ __forceinline__ float sig_fast(float x) {
    return fmaf(0.5f, tanh_fast(0.5f * x), 0.5f);
}

// ---------------------------------------------------------------------------
// Kernel 2: TWO threads per batch element (lanes 2k / 2k+1).
//   role 0 ("lo") owns hidden units {0,1,2}; role 1 ("hi") owns {2,3,4}
//   (unit 2 duplicated -> perfectly uniform control flow, no divergence).
// Each thread: 6 gate-pair f32x2 chains per layer. h exchange: 2x shfl_xor.
// hi's weight columns are stored permuted (2,3,4,0,1) so the thread-local
// h-vector [own0,own1,own2,recv0,recv1] feeds chains with no reassembly.
// All weights in 16B-aligned shared blocks -> LDS.128 only.
// ---------------------------------------------------------------------------
__global__ void __launch_bounds__(256)
lstm_fused_kernel(const float* __restrict__ x,
                  const float* __restrict__ Wih0, const float* __restrict__ Whh0,
                  const float* __restrict__ bih0, const float* __restrict__ bhh0,
                  const float* __restrict__ Wih1, const float* __restrict__ Whh1,
                  const float* __restrict__ bih1, const float* __restrict__ bhh1,
                  float* __restrict__ out)
{
    // [role][pair][slot]; layer0 slots: B, Wih, Whh c0..c4, pad  (8 u64 = 64B)
    //                     layer1 slots: B, Wih1 c0..c4, Whh1 c0..c4, pad (12 u64 = 96B)
    __shared__ __align__(16) u64 sL0[2][6][8];
    __shared__ __align__(16) u64 sL1[2][6][12];
    __shared__ __align__(16) u64 sWeffP[2][SEQ_N];
    __shared__ float sWeffS[2][SEQ_N];

    const int t = threadIdx.x;

    // ---- build role-specialized packed weight tables ----
    if (t < 12) {
        const int r = t / 6, p = t % 6;
        const int q = p >> 1;                       // unit slot 0..2
        const int j = (r == 0) ? q : q + 2;         // unit id: lo {0,1,2}, hi {2,3,4}
        int rowA, rowB;
        if ((p & 1) == 0) { rowA = j;      rowB = 5 + j;  }   // (i_j, f_j)
        else              { rowA = 10 + j; rowB = 15 + j; }   // (g_j, o_j)

        sL0[r][p][0] = pack2(bih0[rowA] + bhh0[rowA], bih0[rowB] + bhh0[rowB]);
        sL0[r][p][1] = pack2(Wih0[rowA], Wih0[rowB]);
        sL1[r][p][0] = pack2(bih1[rowA] + bhh1[rowA], bih1[rowB] + bhh1[rowB]);
        #pragma unroll
        for (int k = 0; k < HID_N; ++k) {
            const int c = (r == 0) ? k : (k + 2) % HID_N;   // column permutation
            sL0[r][p][2 + k] = pack2(Whh0[rowA * HID_N + c], Whh0[rowB * HID_N + c]);
            sL1[r][p][1 + k] = pack2(Wih1[rowA * HID_N + c], Wih1[rowB * HID_N + c]);
            sL1[r][p][6 + k] = pack2(Whh1[rowA * HID_N + c], Whh1[rowB * HID_N + c]);
        }
        sL0[r][p][7]  = 0ull;
        sL1[r][p][11] = 0ull;
    }
    for (int s = t; s < SEQ_N; s += blockDim.x) {
        sWeffP[0][s] = pack2(g_Weff[5 * s + 0], g_Weff[5 * s + 1]);
        sWeffP[1][s] = pack2(g_Weff[5 * s + 2], g_Weff[5 * s + 3]);
        sWeffS[0][s] = 0.0f;
        sWeffS[1][s] = g_Weff[5 * s + 4];
    }
    __syncthreads();

    const int gid = blockIdx.x * blockDim.x + t;
    const int e   = gid >> 1;          // batch element
    const int r   = gid & 1;           // role
    const float* __restrict__ xr = x + (size_t)e * SEQ_N;

    const u64 (*__restrict__ L0)[8]  = sL0[r];
    const u64 (*__restrict__ L1)[12] = sL1[r];
    const u64*   __restrict__ WfP    = sWeffP[r];
    const float* __restrict__ WfS    = sWeffS[r];

    // thread-local role-ordered h vectors (broadcast-packed) + own-cell state
    u64 h0v[HID_N], h1v[HID_N];
    float c0[3], c1[3];
    #pragma unroll
    for (int k = 0; k < HID_N; ++k) { h0v[k] = 0ull; h1v[k] = 0ull; }
    #pragma unroll
    for (int q = 0; q < 3; ++q) { c0[q] = 0.f; c1[q] = 0.f; }

    u64 acc2 = 0ull;
    float accS = 0.0f;

    #pragma unroll 1
    for (int s = 0; s < SEQ_N; ++s) {
        const float xin = __ldg(&xr[s]);
        const u64 xx = pack2(xin, xin);

        // ---- layer 0: 6 packed gate-pair chains ----
        u64 ga[6];
        #pragma unroll
        for (int p = 0; p < 6; ++p) {
            u64 a = fma2(L0[p][1], xx, L0[p][0]);
            #pragma unroll
            for (int k = 0; k < HID_N; ++k)
                a = fma2(L0[p][2 + k], h0v[k], a);
            ga[p] = a;
        }
        // ---- layer 0 activations (own 3 units) ----
        float hu[3];
        #pragma unroll
        for (int q = 0; q < 3; ++q) {
            float iv, fv, gv, ov;
            unpack2(ga[2 * q],     iv, fv);
            unpack2(ga[2 * q + 1], gv, ov);
            float ig = sig_fast(iv), fg = sig_fast(fv);
            float gg = tanh_fast(gv), og = sig_fast(ov);
            float c = fmaf(fg, c0[q], ig * gg);
            c0[q] = c;
            hu[q] = og * tanh_fast(c);
        }
        // ---- exchange: lo sends (h0,h1), hi sends (h3,h4) ----
        {
            float sA = r ? hu[1] : hu[0];
            float sB = r ? hu[2] : hu[1];
            float ra = __shfl_xor_sync(0xffffffffu, sA, 1);
            float rb = __shfl_xor_sync(0xffffffffu, sB, 1);
            h0v[0] = pack2(hu[0], hu[0]);
            h0v[1] = pack2(hu[1], hu[1]);
            h0v[2] = pack2(hu[2], hu[2]);
            h0v[3] = pack2(ra, ra);
            h0v[4] = pack2(rb, rb);
        }

        // ---- layer 1: 6 packed gate-pair chains ----
        #pragma unroll
        for (int p = 0; p < 6; ++p) {
            u64 a = L1[p][0];
            #pragma unroll
            for (int k = 0; k < HID_N; ++k)
                a = fma2(L1[p][1 + k], h0v[k], a);
            #pragma unroll
            for (int k = 0; k < HID_N; ++k)
                a = fma2(L1[p][6 + k], h1v[k], a);
            ga[p] = a;
        }
        // ---- layer 1 activations ----
        #pragma unroll
        for (int q = 0; q < 3; ++q) {
            float iv, fv, gv, ov;
            unpack2(ga[2 * q],     iv, fv);
            unpack2(ga[2 * q + 1], gv, ov);
            float ig = sig_fast(iv), fg = sig_fast(fv);
            float gg = tanh_fast(gv), og = sig_fast(ov);
            float c = fmaf(fg, c1[q], ig * gg);
            c1[q] = c;
            hu[q] = og * tanh_fast(c);
        }
        // ---- folded head: lo does (h0,h1)+0*h2 ; hi does (h2,h3)+w4*h4 ----
        acc2 = fma2(pack2(hu[0], hu[1]), WfP[s], acc2);
        accS = fmaf(hu[2], WfS[s], accS);

        // ---- exchange layer-1 h ----
        {
            float sA = r ? hu[1] : hu[0];
            float sB = r ? hu[2] : hu[1];
            float ra = __shfl_xor_sync(0xffffffffu, sA, 1);
            float rb = __shfl_xor_sync(0xffffffffu, sB, 1);
            h1v[0] = pack2(hu[0], hu[0]);
            h1v[1] = pack2(hu[1], hu[1]);
            h1v[2] = pack2(hu[2], hu[2]);
            h1v[3] = pack2(ra, ra);
            h1v[4] = pack2(rb, rb);
        }
    }

    // combine the two partial head sums; role 0 writes
    float alo, ahi;
    unpack2(acc2, alo, ahi);
    float part = accS + alo + ahi;
    float tot  = part + __shfl_xor_sync(0xffffffffu, part, 1);
    if (r == 0)
        out[e] = tot + g_beff;
}

// ---------------------------------------------------------------------------
// Harness entry. Inputs in metadata order:
// x, Wih0, Whh0, bih0, bhh0, Wih1, Whh1, bih1, bhh1, W1, b1, W2, b2
// ---------------------------------------------------------------------------
extern "C" void kernel_launch(void* const* d_in, const int* in_sizes, int n_in,
                              void* d_out, int out_size)
{
    const float* x    = (const float*)d_in[0];
    const float* Wih0 = (const float*)d_in[1];
    const float* Whh0 = (const float*)d_in[2];
    const float* bih0 = (const float*)d_in[3];
    const float* bhh0 = (const float*)d_in[4];
    const float* Wih1 = (const float*)d_in[5];
    const float* Whh1 = (const float*)d_in[6];
    const float* bih1 = (const float*)d_in[7];
    const float* bhh1 = (const float*)d_in[8];
    const float* W1   = (const float*)d_in[9];
    const float* b1   = (const float*)d_in[10];
    const float* W2   = (const float*)d_in[11];
    const float* b2   = (const float*)d_in[12];
    float* out = (float*)d_out;

    weff_kernel<<<(FLAT_N + 511) / 512, 512>>>(W1, b1, W2, b2);

    // 32768 threads: 2 per batch element, 256/block -> 128 blocks (2 warps/SMSP)
    lstm_fused_kernel<<<(BATCH_N * 2) / 256, 256>>>(x, Wih0, Whh0, bih0, bhh0,
                                                    Wih1, Whh1, bih1, bhh1, out);
}

// round 7
// speedup vs baseline: 2.6189x; 1.6009x over previous
#include <cuda_runtime.h>
#include <cstddef>

#define BATCH_N 16384
#define SEQ_N   512
#define HID_N   5
#define FLAT_N  2560        // SEQ_N*HID_N

// Collapsed linear head: Weff = W2 @ W1 (1 x 2560), beff = W2@b1 + b2
__device__ float g_Weff[FLAT_N];
__device__ float g_beff;

// ---------------------------------------------------------------------------
// Kernel 1: collapse the two linear layers (no nonlinearity between them).
// ---------------------------------------------------------------------------
__global__ void weff_kernel(const float* __restrict__ W1,
                            const float* __restrict__ b1,
                            const float* __restrict__ W2,
                            const float* __restrict__ b2)
{
    int j = blockIdx.x * blockDim.x + threadIdx.x;
    if (j < FLAT_N) {
        float acc = 0.0f;
        #pragma unroll 8
        for (int k = 0; k < 512; ++k)
            acc = fmaf(W2[k], W1[(size_t)k * FLAT_N + j], acc);
        g_Weff[j] = acc;
    }
    if (j == 0) {
        float acc = b2[0];
        for (int k = 0; k < 512; ++k)
            acc = fmaf(W2[k], b1[k], acc);
        g_beff = acc;
    }
}

// ---------------------------------------------------------------------------
// Packed f32x2 + fast-activation primitives
// ---------------------------------------------------------------------------
typedef unsigned long long u64;

__device__ __forceinline__ u64 pack2(float lo, float hi) {
    u64 r; asm("mov.b64 %0, {%1, %2};" : "=l"(r) : "f"(lo), "f"(hi)); return r;
}
__device__ __forceinline__ void unpack2(u64 v, float& lo, float& hi) {
    asm("mov.b64 {%0, %1}, %2;" : "=f"(lo), "=f"(hi) : "l"(v));
}
__device__ __forceinline__ u64 fma2(u64 a, u64 b, u64 c) {
    u64 d; asm("fma.rn.f32x2 %0, %1, %2, %3;" : "=l"(d) : "l"(a), "l"(b), "l"(c)); return d;
}
__device__ __forceinline__ u64 mul2(u64 a, u64 b) {
    u64 d; asm("mul.rn.f32x2 %0, %1, %2;" : "=l"(d) : "l"(a), "l"(b)); return d;
}
__device__ __forceinline__ float tanh_fast(float x) {
    float y; asm("tanh.approx.f32 %0, %1;" : "=f"(y) : "f"(x)); return y;
}
__device__ __forceinline__ float sig_fast(float x) {
    return fmaf(0.5f, tanh_fast(0.5f * x), 0.5f);
}

// ---------------------------------------------------------------------------
// Kernel 2: TWO threads per batch element (lanes 2k / 2k+1).
//   role 0 owns hidden units {0,1,2}; role 1 owns {2,3,4} (unit 2 duplicated).
// Layer-1 weights (66 u64) live in REGISTERS (explicit pre-loop hoist).
// Layer-0 weights (42 u64) stay in shared (LDS.128).
// x is read as float4 (1 LDG per 4 steps).
// ---------------------------------------------------------------------------
__global__ void __launch_bounds__(256)
lstm_fused_kernel(const float* __restrict__ x,
                  const float* __restrict__ Wih0, const float* __restrict__ Whh0,
                  const float* __restrict__ bih0, const float* __restrict__ bhh0,
                  const float* __restrict__ Wih1, const float* __restrict__ Whh1,
                  const float* __restrict__ bih1, const float* __restrict__ bhh1,
                  float* __restrict__ out)
{
    // [role][pair][slot]; layer0 slots: B, Wih, Whh c0..c4, pad  (8 u64 = 64B)
    __shared__ __align__(16) u64 sL0[2][6][8];
    __shared__ __align__(16) u64 sL1[2][6][12];
    __shared__ __align__(16) u64 sWeffP[2][SEQ_N];
    __shared__ float sWeffS[2][SEQ_N];

    const int t = threadIdx.x;

    // ---- build role-specialized packed weight tables ----
    if (t < 12) {
        const int r = t / 6, p = t % 6;
        const int q = p >> 1;                       // unit slot 0..2
        const int j = (r == 0) ? q : q + 2;         // unit id: lo {0,1,2}, hi {2,3,4}
        int rowA, rowB;
        if ((p & 1) == 0) { rowA = j;      rowB = 5 + j;  }   // (i_j, f_j)
        else              { rowA = 10 + j; rowB = 15 + j; }   // (g_j, o_j)

        sL0[r][p][0] = pack2(bih0[rowA] + bhh0[rowA], bih0[rowB] + bhh0[rowB]);
        sL0[r][p][1] = pack2(Wih0[rowA], Wih0[rowB]);
        sL1[r][p][0] = pack2(bih1[rowA] + bhh1[rowA], bih1[rowB] + bhh1[rowB]);
        #pragma unroll
        for (int k = 0; k < HID_N; ++k) {
            const int c = (r == 0) ? k : (k + 2) % HID_N;   // column permutation
            sL0[r][p][2 + k] = pack2(Whh0[rowA * HID_N + c], Whh0[rowB * HID_N + c]);
            sL1[r][p][1 + k] = pack2(Wih1[rowA * HID_N + c], Wih1[rowB * HID_N + c]);
            sL1[r][p][6 + k] = pack2(Whh1[rowA * HID_N + c], Whh1[rowB * HID_N + c]);
        }
        sL0[r][p][7]  = 0ull;
        sL1[r][p][11] = 0ull;
    }
    for (int s = t; s < SEQ_N; s += blockDim.x) {
        sWeffP[0][s] = pack2(g_Weff[5 * s + 0], g_Weff[5 * s + 1]);
        sWeffP[1][s] = pack2(g_Weff[5 * s + 2], g_Weff[5 * s + 3]);
        sWeffS[0][s] = 0.0f;
        sWeffS[1][s] = g_Weff[5 * s + 4];
    }
    __syncthreads();

    const int gid = blockIdx.x * blockDim.x + t;
    const int e   = gid >> 1;          // batch element
    const int r   = gid & 1;           // role
    const float4* __restrict__ xr4 = (const float4*)(x + (size_t)e * SEQ_N);

    const u64 (*__restrict__ L0)[8] = sL0[r];
    const u64*   __restrict__ WfP   = sWeffP[r];
    const float* __restrict__ WfS   = sWeffS[r];

    // ---- hoist layer-1 weights into registers (66 u64 = 132 regs) ----
    u64 w1[6][11];
    {
        const u64 (*__restrict__ L1s)[12] = sL1[r];
        #pragma unroll
        for (int p = 0; p < 6; ++p)
            #pragma unroll
            for (int k = 0; k < 11; ++k)
                w1[p][k] = L1s[p][k];
    }

    const u64 HALF2 = pack2(0.5f, 0.5f);

    u64 h0v[HID_N], h1v[HID_N];
    float c0[3], c1[3];
    #pragma unroll
    for (int k = 0; k < HID_N; ++k) { h0v[k] = 0ull; h1v[k] = 0ull; }
    #pragma unroll
    for (int q = 0; q < 3; ++q) { c0[q] = 0.f; c1[q] = 0.f; }

    u64 acc2 = 0ull;
    float accS = 0.0f;

    #pragma unroll 1
    for (int s4 = 0; s4 < SEQ_N / 4; ++s4) {
        const float4 xq = __ldg(&xr4[s4]);

        #pragma unroll
        for (int su = 0; su < 4; ++su) {
            const int s = 4 * s4 + su;
            const float xin = (su == 0) ? xq.x : (su == 1) ? xq.y : (su == 2) ? xq.z : xq.w;
            const u64 xx = pack2(xin, xin);

            // ---- layer 0: 6 packed gate-pair chains (weights via LDS.128) ----
            u64 ga[6];
            #pragma unroll
            for (int p = 0; p < 6; ++p) {
                u64 a = fma2(L0[p][1], xx, L0[p][0]);
                #pragma unroll
                for (int k = 0; k < HID_N; ++k)
                    a = fma2(L0[p][2 + k], h0v[k], a);
                ga[p] = a;
            }
            // ---- layer 0 activations (own 3 units) ----
            float hu[3];
            #pragma unroll
            for (int q = 0; q < 3; ++q) {
                float iv, fv, gv, ov, ig, fg;
                unpack2(mul2(ga[2 * q], HALF2), iv, fv);
                float ti = tanh_fast(iv), tf = tanh_fast(fv);
                unpack2(fma2(pack2(ti, tf), HALF2, HALF2), ig, fg);
                unpack2(ga[2 * q + 1], gv, ov);
                float gg = tanh_fast(gv);
                float og = sig_fast(ov);
                float c = fmaf(fg, c0[q], ig * gg);
                c0[q] = c;
                hu[q] = og * tanh_fast(c);
            }
            // ---- exchange: lo sends (h0,h1), hi sends (h3,h4) ----
            {
                float sA = r ? hu[1] : hu[0];
                float sB = r ? hu[2] : hu[1];
                float ra = __shfl_xor_sync(0xffffffffu, sA, 1);
                float rb = __shfl_xor_sync(0xffffffffu, sB, 1);
                h0v[0] = pack2(hu[0], hu[0]);
                h0v[1] = pack2(hu[1], hu[1]);
                h0v[2] = pack2(hu[2], hu[2]);
                h0v[3] = pack2(ra, ra);
                h0v[4] = pack2(rb, rb);
            }

            // ---- layer 1: 6 packed gate-pair chains (weights in REGISTERS) ----
            #pragma unroll
            for (int p = 0; p < 6; ++p) {
                u64 a = w1[p][0];
                #pragma unroll
                for (int k = 0; k < HID_N; ++k)
                    a = fma2(w1[p][1 + k], h0v[k], a);
                #pragma unroll
                for (int k = 0; k < HID_N; ++k)
                    a = fma2(w1[p][6 + k], h1v[k], a);
                ga[p] = a;
            }
            // ---- layer 1 activations ----
            #pragma unroll
            for (int q = 0; q < 3; ++q) {
                float iv, fv, gv, ov, ig, fg;
                unpack2(mul2(ga[2 * q], HALF2), iv, fv);
                float ti = tanh_fast(iv), tf = tanh_fast(fv);
                unpack2(fma2(pack2(ti, tf), HALF2, HALF2), ig, fg);
                unpack2(ga[2 * q + 1], gv, ov);
                float gg = tanh_fast(gv);
                float og = sig_fast(ov);
                float c = fmaf(fg, c1[q], ig * gg);
                c1[q] = c;
                hu[q] = og * tanh_fast(c);
            }
            // ---- folded head ----
            acc2 = fma2(pack2(hu[0], hu[1]), WfP[s], acc2);
            accS = fmaf(hu[2], WfS[s], accS);

            // ---- exchange layer-1 h ----
            {
                float sA = r ? hu[1] : hu[0];
                float sB = r ? hu[2] : hu[1];
                float ra = __shfl_xor_sync(0xffffffffu, sA, 1);
                float rb = __shfl_xor_sync(0xffffffffu, sB, 1);
                h1v[0] = pack2(hu[0], hu[0]);
                h1v[1] = pack2(hu[1], hu[1]);
                h1v[2] = pack2(hu[2], hu[2]);
                h1v[3] = pack2(ra, ra);
                h1v[4] = pack2(rb, rb);
            }
        }
    }

    // combine the two partial head sums; role 0 writes
    float alo, ahi;
    unpack2(acc2, alo, ahi);
    float part = accS + alo + ahi;
    float tot  = part + __shfl_xor_sync(0xffffffffu, part, 1);
    if (r == 0)
        out[e] = tot + g_beff;
}

// ---------------------------------------------------------------------------
// Harness entry. Inputs in metadata order:
// x, Wih0, Whh0, bih0, bhh0, Wih1, Whh1, bih1, bhh1, W1, b1, W2, b2
// ---------------------------------------------------------------------------
extern "C" void kernel_launch(void* const* d_in, const int* in_sizes, int n_in,
                              void* d_out, int out_size)
{
    const float* x    = (const float*)d_in[0];
    const float* Wih0 = (const float*)d_in[1];
    const float* Whh0 = (const float*)d_in[2];
    const float* bih0 = (const float*)d_in[3];
    const float* bhh0 = (const float*)d_in[4];
    const float* Wih1 = (const float*)d_in[5];
    const float* Whh1 = (const float*)d_in[6];
    const float* bih1 = (const float*)d_in[7];
    const float* bhh1 = (const float*)d_in[8];
    const float* W1   = (const float*)d_in[9];
    const float* b1   = (const float*)d_in[10];
    const float* W2   = (const float*)d_in[11];
    const float* b2   = (const float*)d_in[12];
    float* out = (float*)d_out;

    weff_kernel<<<(FLAT_N + 511) / 512, 512>>>(W1, b1, W2, b2);

    // 32768 threads: 2 per batch element, 256/block -> 128 blocks (2 warps/SMSP)
    lstm_fused_kernel<<<(BATCH_N * 2) / 256, 256>>>(x, Wih0, Whh0, bih0, bhh0,
                                                    Wih1, Whh1, bih1, bhh1, out);
}